// round 9
// baseline (speedup 1.0000x reference)
#include <cuda_runtime.h>
#include <cstdint>

// LanczosInterpolationLayer: x f32 [32,3,512,512] -> Lanczos4 2x upsample ->
// per-image range renormalize -> *255 -> uint8 (saturating trunc) -> f32 out.
//
// R8 (189us; pass2=110.6us, issue 79.7% = cap). R9 issue-count surgery:
//  - USTR=42: stage-C window loads as LDS.64 (half the LDS issues).
//  - full unroll stage-C loops -> immediate smem/gmem offsets.
//  - stage A: one division + incremental (r+=6,c+=16) indexing.

#define NIMG   32
#define NCH    96
#define IN_SZ  512
#define OUT_SZ 1024
#define TILE_W 64           // output cols per block
#define TILE_H 128          // output rows per block
#define PAT_W  40           // input patch cols (32 + 8 halo)
#define PAT_H  72           // input patch rows (64 + 8 halo)
#define PSTR   41           // s_in stride (odd -> conflict-free vertical)
#define USTR   42           // s_ut stride (even -> 8B-aligned windows)
#define SLOTS  128          // blocks per channel (16 x * 8 y)

__device__ float g_pmin[NCH * SLOTS];
__device__ float g_pmax[NCH * SLOTS];

// Normalized Lanczos4 weights, even phase (output 2m): tap j hits input m-4+j.
#define WE0 (-0.0039706f)
#define WE1 ( 0.0314676f)
#define WE2 (-0.0916620f)
#define WE3 ( 0.2826868f)
#define WE4 ( 0.8933939f)
#define WE5 (-0.1523043f)
#define WE6 ( 0.0554435f)
#define WE7 (-0.0150549f)

#define EVEN8(a0,a1,a2,a3,a4,a5,a6,a7) \
  fmaf((a7), WE7, fmaf((a6), WE6, fmaf((a5), WE5, fmaf((a4), WE4, \
  fmaf((a3), WE3, fmaf((a2), WE2, fmaf((a1), WE1, (a0) * WE0)))))))
#define ODD8(a1,a2,a3,a4,a5,a6,a7,a8) \
  fmaf((a8), WE0, fmaf((a7), WE1, fmaf((a6), WE2, fmaf((a5), WE3, \
  fmaf((a4), WE4, fmaf((a3), WE5, fmaf((a2), WE6, (a1) * WE7)))))))

template <bool WRITE>
__global__ void __launch_bounds__(256, 5)
k_resize(const float* __restrict__ x, float* __restrict__ out)
{
    __shared__ float s_in[PAT_H * PSTR];    // input patch  [irow][icol]
    __shared__ float s_ut[TILE_H * USTR];   // H-resampled  [orow][icol]
    __shared__ float s_red[16];

    const int tid = threadIdx.x;
    const int bc  = blockIdx.z;                  // image*3 + channel
    const int m0  = blockIdx.y * (TILE_H / 2);   // input row base
    const int n0  = blockIdx.x * (TILE_W / 2);   // input col base
    const float* src = x + (size_t)bc * (IN_SZ * IN_SZ);

    // ---- pass 2 only: reduce this image's 384 min/max partials ----
    if (WRITE) {
        const int img3 = (bc / 3) * 3;
        float a = __int_as_float(0x7f800000);
        float b = -a;
        #pragma unroll
        for (int i = 0; i < 2; i++) {
            int idx = tid + 256 * i;
            if (idx < 3 * SLOTS) {
                a = fminf(a, g_pmin[img3 * SLOTS + idx]);
                b = fmaxf(b, g_pmax[img3 * SLOTS + idx]);
            }
        }
        #pragma unroll
        for (int m = 16; m; m >>= 1) {
            a = fminf(a, __shfl_xor_sync(0xffffffffu, a, m));
            b = fmaxf(b, __shfl_xor_sync(0xffffffffu, b, m));
        }
        if ((tid & 31) == 0) {
            s_red[tid >> 5]       = a;
            s_red[8 + (tid >> 5)] = b;
        }
    }

    // ---- stage A: load input patch with replicate border ----
    {
        int r = tid / PAT_W;
        int c = tid - r * PAT_W;
        #pragma unroll
        for (int i = 0; i < 12; i++) {
            if (r < PAT_H) {
                int gy = min(max(m0 - 4 + r, 0), IN_SZ - 1);
                int gx = min(max(n0 - 4 + c, 0), IN_SZ - 1);
                s_in[r * PSTR + c] = src[gy * IN_SZ + gx];
            }
            r += 6; c += 16;               // 256 = 6*40 + 16
            if (c >= PAT_W) { c -= PAT_W; r += 1; }
        }
    }
    __syncthreads();

    // renorm collapsed: f(v) = min(P1*v, P3*v + Q3), then clamp+trunc.
    float P1 = 255.f, P3 = 255.f, Q3 = 0.f;
    if (WRITE) {
        float mn = s_red[0], mx = s_red[8];
        #pragma unroll
        for (int i = 1; i < 8; i++) {
            mn = fminf(mn, s_red[i]);
            mx = fmaxf(mx, s_red[8 + i]);
        }
        if ((mx - mn) > 1.0f) {
            const float ott = 1.0f / 255.0f;
            const float ubt = -10.0f / 255.0f;
            float otr = mx - 1.0f;
            float s1 = ott / (otr != 0.0f ? otr : 1.0f);
            float c1 = 1.0f - ott;
            float c2 = 1.0f - ubt;
            P1 = 255.0f * c1 * c2;
            P3 = 255.0f * s1 * c2;
            Q3 = 255.0f * c2 * (c1 - s1);
        }
    }

    // ---- stage B: vertical (height) resample -> s_ut[orow][icol] ----
    for (int t = tid; t < PAT_W * 8; t += 256) {
        int g  = t / PAT_W;
        int ic = t - g * PAT_W;
        int mb = g * 8;
        const float* p = &s_in[mb * PSTR + ic];
        float w0 = p[0 * PSTR], w1 = p[1 * PSTR], w2 = p[2 * PSTR];
        float w3 = p[3 * PSTR], w4 = p[4 * PSTR], w5 = p[5 * PSTR];
        float w6 = p[6 * PSTR], w7 = p[7 * PSTR], w8 = p[8 * PSTR];
        float* q = &s_ut[2 * mb * USTR + ic];
        #pragma unroll
        for (int mm = 0; mm < 8; mm++) {
            q[(2 * mm)     * USTR] = EVEN8(w0, w1, w2, w3, w4, w5, w6, w7);
            q[(2 * mm + 1) * USTR] = ODD8(w1, w2, w3, w4, w5, w6, w7, w8);
            w0 = w1; w1 = w2; w2 = w3; w3 = w4;
            w4 = w5; w5 = w6; w6 = w7; w7 = w8;
            if (mm < 7) w8 = p[(mm + 9) * PSTR];
        }
    }
    __syncthreads();

    // ---- stage C ----
    if (!WRITE) {
        // full-row mapping: thread = (orow, col half); 12x LDS.64 window
        const int orr = tid & (TILE_H - 1);
        const int h   = tid >> 7;
        const float2* wp =
            reinterpret_cast<const float2*>(&s_ut[orr * USTR + 16 * h]);

        float win[24];
        #pragma unroll
        for (int j = 0; j < 12; j++) {
            float2 t2 = wp[j];
            win[2 * j] = t2.x; win[2 * j + 1] = t2.y;
        }

        float vmin = __int_as_float(0x7f800000);
        float vmax = -vmin;
        #pragma unroll
        for (int n = 0; n < 16; n++) {
            float e = EVEN8(win[n],     win[n + 1], win[n + 2], win[n + 3],
                            win[n + 4], win[n + 5], win[n + 6], win[n + 7]);
            float o = ODD8 (win[n + 1], win[n + 2], win[n + 3], win[n + 4],
                            win[n + 5], win[n + 6], win[n + 7], win[n + 8]);
            vmin = fminf(vmin, fminf(e, o));
            vmax = fmaxf(vmax, fmaxf(e, o));
        }
        #pragma unroll
        for (int m = 16; m; m >>= 1) {
            vmin = fminf(vmin, __shfl_xor_sync(0xffffffffu, vmin, m));
            vmax = fmaxf(vmax, __shfl_xor_sync(0xffffffffu, vmax, m));
        }
        int w5 = tid >> 5, l = tid & 31;
        if (l == 0) { s_red[w5] = vmin; s_red[8 + w5] = vmax; }
        __syncthreads();
        if (tid == 0) {
            float a = s_red[0], b = s_red[8];
            #pragma unroll
            for (int i = 1; i < 8; i++) {
                a = fminf(a, s_red[i]);
                b = fmaxf(b, s_red[8 + i]);
            }
            int slot = blockIdx.y * 16 + blockIdx.x;
            g_pmin[bc * SLOTS + slot] = a;
            g_pmax[bc * SLOTS + slot] = b;
        }
    } else {
        // coalesced mapping: thread = (row, 4-px segment); warp = 2 rows.
        const int seg  = tid & 15;          // 16 segments * 4 px = 64 cols
        const int rsub = tid >> 4;          // 16 rows per iteration
        const float2* wbase =
            reinterpret_cast<const float2*>(&s_ut[rsub * USTR + 2 * seg]);
        float* dstb = out + ((size_t)bc * OUT_SZ + blockIdx.y * TILE_H + rsub)
                          * OUT_SZ + blockIdx.x * TILE_W + seg * 4;
        #pragma unroll
        for (int it = 0; it < 8; it++) {
            const float2* wp = wbase + it * (16 * USTR / 2);
            float2 ab = wp[0], cd = wp[1], ef = wp[2], gh = wp[3], ij = wp[4];
            float w0 = ab.x, w1 = ab.y, w2 = cd.x, w3 = cd.y, w4 = ef.x,
                  w5 = ef.y, w6 = gh.x, w7 = gh.y, w8 = ij.x, w9 = ij.y;
            float p0 = EVEN8(w0, w1, w2, w3, w4, w5, w6, w7);
            float p1 = ODD8 (w1, w2, w3, w4, w5, w6, w7, w8);
            float p2 = EVEN8(w1, w2, w3, w4, w5, w6, w7, w8);
            float p3 = ODD8 (w2, w3, w4, w5, w6, w7, w8, w9);
            float f0 = fminf(fminf(p0 * P1, fmaf(p0, P3, Q3)), 255.0f);
            float f1 = fminf(fminf(p1 * P1, fmaf(p1, P3, Q3)), 255.0f);
            float f2 = fminf(fminf(p2 * P1, fmaf(p2, P3, Q3)), 255.0f);
            float f3 = fminf(fminf(p3 * P1, fmaf(p3, P3, Q3)), 255.0f);
            // cvt.rzi.u32 clamps negatives to 0; fminf clamped the top
            f0 = (float)__float2uint_rz(f0);
            f1 = (float)__float2uint_rz(f1);
            f2 = (float)__float2uint_rz(f2);
            f3 = (float)__float2uint_rz(f3);
            *reinterpret_cast<float4*>(dstb + (size_t)it * 16 * OUT_SZ) =
                make_float4(f0, f1, f2, f3);
        }
    }
}

extern "C" void kernel_launch(void* const* d_in, const int* in_sizes, int n_in,
                              void* d_out, int out_size)
{
    const float* x = (const float*)d_in[0];
    float* out = (float*)d_out;

    dim3 grid(OUT_SZ / TILE_W, OUT_SZ / TILE_H, NCH);
    k_resize<false><<<grid, 256>>>(x, nullptr);
    k_resize<true ><<<grid, 256>>>(x, out);
}

// round 11
// speedup vs baseline: 1.0182x; 1.0182x over previous
#include <cuda_runtime.h>
#include <cstdint>

// LanczosInterpolationLayer: x f32 [32,3,512,512] -> Lanczos4 2x upsample ->
// per-image range renormalize -> *255 -> uint8 (saturating trunc) -> f32 out.
//
// R10 failed (rel_err 3e-3): magic-floor tie-to-even sent the f==255.0 clamp
// cohort (odd integer) to 254. R11: clamp bottom -> floor -> clamp top AFTER
// (saturated 256..265 floor to themselves, then min to 255; f=0 is an even
// tie and rounds correctly). Rest identical to R8 + CVT-free quantize.

#define NIMG   32
#define NCH    96
#define IN_SZ  512
#define OUT_SZ 1024
#define TILE_W 64           // output cols per block
#define TILE_H 128          // output rows per block
#define PAT_W  40           // input patch cols (32 + 8 halo)
#define PAT_H  72           // input patch rows (64 + 8 halo)
#define PSTR   41           // s_in stride (odd -> conflict-free)
#define USTR   41           // s_ut stride [orow][icol] (conflict-free)
#define SLOTS  128          // blocks per channel (16 x * 8 y)

__device__ float g_pmin[NCH * SLOTS];
__device__ float g_pmax[NCH * SLOTS];

// Normalized Lanczos4 weights, even phase (output 2m): tap j hits input m-4+j.
#define WE0 (-0.0039706f)
#define WE1 ( 0.0314676f)
#define WE2 (-0.0916620f)
#define WE3 ( 0.2826868f)
#define WE4 ( 0.8933939f)
#define WE5 (-0.1523043f)
#define WE6 ( 0.0554435f)
#define WE7 (-0.0150549f)

#define EVEN8(a0,a1,a2,a3,a4,a5,a6,a7) \
  fmaf((a7), WE7, fmaf((a6), WE6, fmaf((a5), WE5, fmaf((a4), WE4, \
  fmaf((a3), WE3, fmaf((a2), WE2, fmaf((a1), WE1, (a0) * WE0)))))))
#define ODD8(a1,a2,a3,a4,a5,a6,a7,a8) \
  fmaf((a8), WE0, fmaf((a7), WE1, fmaf((a6), WE2, fmaf((a5), WE3, \
  fmaf((a4), WE4, fmaf((a3), WE5, fmaf((a2), WE6, (a1) * WE7)))))))

// CVT-free floor for f in [0, ~300): RN(f - 0.5) via the 1.5*2^23 magic add.
// Exact-integer ties only matter at mass points; callers clamp the 255 mass
// point AFTER this (and f=0 is an even tie -> correct).
static __device__ __forceinline__ float floor_pos(float f) {
    float t = (f - 0.49999997f) + 12582912.0f;
    return t - 12582912.0f;
}

template <bool WRITE>
__global__ void __launch_bounds__(256, 5)
k_resize(const float* __restrict__ x, float* __restrict__ out)
{
    __shared__ float s_in[PAT_H * PSTR];    // input patch  [irow][icol]
    __shared__ float s_ut[TILE_H * USTR];   // H-resampled  [orow][icol]
    __shared__ float s_red[16];

    const int tid = threadIdx.x;
    const int bc  = blockIdx.z;                  // image*3 + channel
    const int m0  = blockIdx.y * (TILE_H / 2);   // input row base
    const int n0  = blockIdx.x * (TILE_W / 2);   // input col base
    const float* src = x + (size_t)bc * (IN_SZ * IN_SZ);

    // ---- pass 2 only: reduce this image's 384 min/max partials ----
    if (WRITE) {
        const int img3 = (bc / 3) * 3;
        float a = __int_as_float(0x7f800000);
        float b = -a;
        #pragma unroll
        for (int i = 0; i < 2; i++) {
            int idx = tid + 256 * i;
            if (idx < 3 * SLOTS) {
                a = fminf(a, g_pmin[img3 * SLOTS + idx]);
                b = fmaxf(b, g_pmax[img3 * SLOTS + idx]);
            }
        }
        #pragma unroll
        for (int m = 16; m; m >>= 1) {
            a = fminf(a, __shfl_xor_sync(0xffffffffu, a, m));
            b = fmaxf(b, __shfl_xor_sync(0xffffffffu, b, m));
        }
        if ((tid & 31) == 0) {
            s_red[tid >> 5]       = a;
            s_red[8 + (tid >> 5)] = b;
        }
    }

    // ---- stage A: load input patch with replicate border ----
    #pragma unroll
    for (int i = 0; i < 12; i++) {
        int idx = tid + 256 * i;
        if (idx < PAT_H * PAT_W) {
            int r = idx / PAT_W;
            int c = idx - r * PAT_W;
            int gy = min(max(m0 - 4 + r, 0), IN_SZ - 1);
            int gx = min(max(n0 - 4 + c, 0), IN_SZ - 1);
            s_in[r * PSTR + c] = src[gy * IN_SZ + gx];
        }
    }
    __syncthreads();

    // renorm collapsed: f(v) = min(P1*v, P3*v + Q3), then clamp+floor.
    float P1 = 255.f, P3 = 255.f, Q3 = 0.f;
    if (WRITE) {
        float mn = s_red[0], mx = s_red[8];
        #pragma unroll
        for (int i = 1; i < 8; i++) {
            mn = fminf(mn, s_red[i]);
            mx = fmaxf(mx, s_red[8 + i]);
        }
        if ((mx - mn) > 1.0f) {
            const float ott = 1.0f / 255.0f;
            const float ubt = -10.0f / 255.0f;
            float otr = mx - 1.0f;
            float s1 = ott / (otr != 0.0f ? otr : 1.0f);
            float c1 = 1.0f - ott;
            float c2 = 1.0f - ubt;
            P1 = 255.0f * c1 * c2;
            P3 = 255.0f * s1 * c2;
            Q3 = 255.0f * c2 * (c1 - s1);
        }
    }

    // ---- stage B: vertical (height) resample -> s_ut[orow][icol] ----
    for (int t = tid; t < PAT_W * 8; t += 256) {
        int g  = t / PAT_W;
        int ic = t - g * PAT_W;
        int mb = g * 8;
        const float* p = &s_in[mb * PSTR + ic];
        float w0 = p[0 * PSTR], w1 = p[1 * PSTR], w2 = p[2 * PSTR];
        float w3 = p[3 * PSTR], w4 = p[4 * PSTR], w5 = p[5 * PSTR];
        float w6 = p[6 * PSTR], w7 = p[7 * PSTR], w8 = p[8 * PSTR];
        float* q = &s_ut[2 * mb * USTR + ic];
        #pragma unroll
        for (int mm = 0; mm < 8; mm++) {
            q[(2 * mm)     * USTR] = EVEN8(w0, w1, w2, w3, w4, w5, w6, w7);
            q[(2 * mm + 1) * USTR] = ODD8(w1, w2, w3, w4, w5, w6, w7, w8);
            w0 = w1; w1 = w2; w2 = w3; w3 = w4;
            w4 = w5; w5 = w6; w6 = w7; w7 = w8;
            if (mm < 7) w8 = p[(mm + 9) * PSTR];
        }
    }
    __syncthreads();

    // ---- stage C ----
    if (!WRITE) {
        // full-row mapping: thread = (orow, col half); contiguous window
        const int orr = tid & (TILE_H - 1);
        const int h   = tid >> 7;
        const float* w = &s_ut[orr * USTR + 16 * h];

        float win[24];
        #pragma unroll
        for (int j = 0; j < 24; j++) win[j] = w[j];

        float vmin = __int_as_float(0x7f800000);
        float vmax = -vmin;
        #pragma unroll
        for (int n = 0; n < 16; n++) {
            float e = EVEN8(win[n],     win[n + 1], win[n + 2], win[n + 3],
                            win[n + 4], win[n + 5], win[n + 6], win[n + 7]);
            float o = ODD8 (win[n + 1], win[n + 2], win[n + 3], win[n + 4],
                            win[n + 5], win[n + 6], win[n + 7], win[n + 8]);
            vmin = fminf(vmin, fminf(e, o));
            vmax = fmaxf(vmax, fmaxf(e, o));
        }
        #pragma unroll
        for (int m = 16; m; m >>= 1) {
            vmin = fminf(vmin, __shfl_xor_sync(0xffffffffu, vmin, m));
            vmax = fmaxf(vmax, __shfl_xor_sync(0xffffffffu, vmax, m));
        }
        int w5 = tid >> 5, l = tid & 31;
        if (l == 0) { s_red[w5] = vmin; s_red[8 + w5] = vmax; }
        __syncthreads();
        if (tid == 0) {
            float a = s_red[0], b = s_red[8];
            #pragma unroll
            for (int i = 1; i < 8; i++) {
                a = fminf(a, s_red[i]);
                b = fmaxf(b, s_red[8 + i]);
            }
            int slot = blockIdx.y * 16 + blockIdx.x;
            g_pmin[bc * SLOTS + slot] = a;
            g_pmax[bc * SLOTS + slot] = b;
        }
    } else {
        // coalesced mapping: thread = (row, 4-px segment); warp = 2 rows.
        const int seg  = tid & 15;          // 16 segments * 4 px = 64 cols
        const int rsub = tid >> 4;          // 16 rows per iteration
        const int ic0  = 2 * seg;           // window start in s_ut cols
        float* dstb = out + ((size_t)bc * OUT_SZ + blockIdx.y * TILE_H + rsub)
                          * OUT_SZ + blockIdx.x * TILE_W + seg * 4;
        #pragma unroll 2
        for (int it = 0; it < 8; it++) {
            const float* w = &s_ut[(it * 16 + rsub) * USTR + ic0];
            float w0 = w[0], w1 = w[1], w2 = w[2], w3 = w[3], w4 = w[4],
                  w5 = w[5], w6 = w[6], w7 = w[7], w8 = w[8], w9 = w[9];
            float p0 = EVEN8(w0, w1, w2, w3, w4, w5, w6, w7);
            float p1 = ODD8 (w1, w2, w3, w4, w5, w6, w7, w8);
            float p2 = EVEN8(w1, w2, w3, w4, w5, w6, w7, w8);
            float p3 = ODD8 (w2, w3, w4, w5, w6, w7, w8, w9);
            // bottom clamp -> floor -> TOP CLAMP AFTER (255 mass point safe)
            float f0 = fmaxf(fminf(p0 * P1, fmaf(p0, P3, Q3)), 0.0f);
            float f1 = fmaxf(fminf(p1 * P1, fmaf(p1, P3, Q3)), 0.0f);
            float f2 = fmaxf(fminf(p2 * P1, fmaf(p2, P3, Q3)), 0.0f);
            float f3 = fmaxf(fminf(p3 * P1, fmaf(p3, P3, Q3)), 0.0f);
            f0 = fminf(floor_pos(f0), 255.0f);
            f1 = fminf(floor_pos(f1), 255.0f);
            f2 = fminf(floor_pos(f2), 255.0f);
            f3 = fminf(floor_pos(f3), 255.0f);
            *reinterpret_cast<float4*>(dstb + (size_t)it * 16 * OUT_SZ) =
                make_float4(f0, f1, f2, f3);
        }
    }
}

extern "C" void kernel_launch(void* const* d_in, const int* in_sizes, int n_in,
                              void* d_out, int out_size)
{
    const float* x = (const float*)d_in[0];
    float* out = (float*)d_out;

    dim3 grid(OUT_SZ / TILE_W, OUT_SZ / TILE_H, NCH);
    k_resize<false><<<grid, 256>>>(x, nullptr);
    k_resize<true ><<<grid, 256>>>(x, out);
}